// round 10
// baseline (speedup 1.0000x reference)
#include <cuda_runtime.h>
#include <math.h>

#define NB 262144
#define NP 8
#define NT 256
#define NBLOCKS (NB / NT)

__device__ double g_part[NBLOCKS];
__device__ unsigned int g_ticket;

__global__ void __launch_bounds__(NT)
ciou_kernel(const float* __restrict__ A, const float* __restrict__ Bm,
            float* __restrict__ out) {
    const int tid = threadIdx.x;
    const int b   = blockIdx.x * NT + tid;

    double val;
    {
        // ---- load both octagons (registers; const indexing everywhere) ----
        float axv[NP], ayv[NP], bxv[NP], byv[NP];
        const float4* pa4 = (const float4*)(A  + (size_t)b * 16);
        const float4* pb4 = (const float4*)(Bm + (size_t)b * 16);
        #pragma unroll
        for (int i = 0; i < 4; i++) {
            float4 fa = pa4[i], fb = pb4[i];
            axv[2*i]   = fa.x; ayv[2*i]   = fa.y;
            axv[2*i+1] = fa.z; ayv[2*i+1] = fa.w;
            bxv[2*i]   = fb.x; byv[2*i]   = fb.y;
            bxv[2*i+1] = fb.z; byv[2*i+1] = fb.w;
        }

        // ---- shoelace areas (vertices CCW by construction) ----
        float area_a = 0.f, area_b = 0.f;
        #pragma unroll
        for (int i = 0; i < NP; i++) {
            int j = (i + 1) & 7;
            area_a += axv[i]*ayv[j] - ayv[i]*axv[j];
            area_b += bxv[i]*byv[j] - byv[i]*bxv[j];
        }
        area_a *= 0.5f; area_b *= 0.5f;

        // ---- intersection area via Green's theorem + Liang-Barsky ----
        // area(A∩B) = 1/2 * sum over boundary sub-segments of cross(P,Q):
        //   * each A edge clipped to the inside of B
        //   * each B edge clipped to the inside of A
        // Order-independent, branch-free, fully register-resident.
        float acc2 = 0.f;

        // A edges clipped against B's half-planes
        #pragma unroll
        for (int i = 0; i < NP; i++) {
            int ik = (i + 1) & 7;
            float px = axv[i],        py = ayv[i];
            float dx = axv[ik] - px,  dy = ayv[ik] - py;
            float t0 = 0.f, t1 = 1.f;
            #pragma unroll
            for (int j = 0; j < NP; j++) {
                int jk = (j + 1) & 7;
                float ex = bxv[jk] - bxv[j], ey = byv[jk] - byv[j];
                float c0 = ex*(py - byv[j]) - ey*(px - bxv[j]); // f(0)
                float cd = ex*dy - ey*dx;                       // df/dt
                float r  = __fdividef(-c0, cd);
                t0 = (cd > 0.f) ? fmaxf(t0, r) : t0;
                t1 = (cd < 0.f) ? fminf(t1, r) : t1;
                if (cd == 0.f && c0 < 0.f) t0 = 1e30f;          // fully outside
            }
            if (t1 > t0) {
                float qx0 = px + t0*dx, qy0 = py + t0*dy;
                float qx1 = px + t1*dx, qy1 = py + t1*dy;
                acc2 += qx0*qy1 - qy0*qx1;
            }
        }
        // B edges clipped against A's half-planes
        #pragma unroll
        for (int i = 0; i < NP; i++) {
            int ik = (i + 1) & 7;
            float px = bxv[i],        py = byv[i];
            float dx = bxv[ik] - px,  dy = byv[ik] - py;
            float t0 = 0.f, t1 = 1.f;
            #pragma unroll
            for (int j = 0; j < NP; j++) {
                int jk = (j + 1) & 7;
                float ex = axv[jk] - axv[j], ey = ayv[jk] - ayv[j];
                float c0 = ex*(py - ayv[j]) - ey*(px - axv[j]);
                float cd = ex*dy - ey*dx;
                float r  = __fdividef(-c0, cd);
                t0 = (cd > 0.f) ? fmaxf(t0, r) : t0;
                t1 = (cd < 0.f) ? fminf(t1, r) : t1;
                if (cd == 0.f && c0 < 0.f) t0 = 1e30f;
            }
            if (t1 > t0) {
                float qx0 = px + t0*dx, qy0 = py + t0*dy;
                float qx1 = px + t1*dx, qy1 = py + t1*dy;
                acc2 += qx0*qy1 - qy0*qx1;
            }
        }
        float inter = fmaxf(0.5f * acc2, 0.f);

        // ---- convex hull of all 16 points (pure-register Jarvis march) ----
        int   si  = 0;
        float spx = axv[0], spy = ayv[0];
        #pragma unroll
        for (int i = 1; i < 16; i++) {
            float pix = (i < 8) ? axv[i] : bxv[i-8];
            float piy = (i < 8) ? ayv[i] : byv[i-8];
            bool better = (piy < spy) || (piy == spy && pix < spx);
            if (better) { si = i; spx = pix; spy = piy; }
        }
        float acc = 0.f, cpx = spx, cpy = spy;
        #pragma unroll 1
        for (int step = 0; step < 16; step++) {
            int   nxt = -1;
            float vnx = 0.f, vny = 0.f, nd2 = 0.f, nxx = 0.f, nxy = 0.f;
            #pragma unroll
            for (int p = 0; p < 16; p++) {
                float pxp = (p < 8) ? axv[p] : bxv[p-8];
                float pyp = (p < 8) ? ayv[p] : byv[p-8];
                float vx = pxp - cpx, vy = pyp - cpy;
                float d2 = vx*vx + vy*vy;
                if (d2 >= 1e-16f) {
                    bool take;
                    if (nxt < 0) take = true;
                    else {
                        float cr = vnx*vy - vny*vx;
                        take = (cr < 0.f) || (cr == 0.f && d2 > nd2);
                    }
                    if (take) { nxt = p; vnx = vx; vny = vy; nd2 = d2;
                                nxx = pxp; nxy = pyp; }
                }
            }
            if (nxt < 0) break;
            acc += cpx*nxy - cpy*nxx;
            if (nxt == si) break;
            cpx = nxx; cpy = nxy;
        }
        float ch = 0.5f * acc;

        // ---- CIoU ----
        float uni = area_a + area_b - inter;
        float iou = inter / uni;
        val = (double)(iou - (ch - uni) / ch);
    }

    // ---- deterministic block reduction (8 warps) ----
    #pragma unroll
    for (int o = 16; o > 0; o >>= 1)
        val += __shfl_down_sync(0xffffffffu, val, o);
    __shared__ double ws[NT / 32];
    __shared__ bool is_last;
    int lane = threadIdx.x & 31;
    int w    = threadIdx.x >> 5;
    if (lane == 0) ws[w] = val;
    __syncthreads();
    if (w == 0) {
        val = (lane < (NT / 32)) ? ws[lane] : 0.0;
        #pragma unroll
        for (int o = 4; o > 0; o >>= 1)
            val += __shfl_down_sync(0xffffffffu, val, o);
        if (lane == 0) g_part[blockIdx.x] = val;
    }

    // ---- last block folds the partials (deterministic fixed-order sum) ----
    __threadfence();
    if (threadIdx.x == 0) {
        unsigned int t = atomicAdd(&g_ticket, 1u);
        is_last = (t == NBLOCKS - 1);
    }
    __syncthreads();
    if (is_last) {
        __threadfence();
        double v = 0.0;
        for (int i = threadIdx.x; i < NBLOCKS; i += NT) v += g_part[i];
        #pragma unroll
        for (int o = 16; o > 0; o >>= 1)
            v += __shfl_down_sync(0xffffffffu, v, o);
        if (lane == 0) ws[w] = v;
        __syncthreads();
        if (w == 0) {
            v = (lane < (NT / 32)) ? ws[lane] : 0.0;
            #pragma unroll
            for (int o = 4; o > 0; o >>= 1)
                v += __shfl_down_sync(0xffffffffu, v, o);
            if (lane == 0) {
                out[0] = (float)(v / (double)NB);
                g_ticket = 0;   // reset for next graph replay
            }
        }
    }
}

extern "C" void kernel_launch(void* const* d_in, const int* in_sizes, int n_in,
                              void* d_out, int out_size) {
    const float* a = (const float*)d_in[0];
    const float* b = (const float*)d_in[1];
    ciou_kernel<<<NBLOCKS, NT>>>(a, b, (float*)d_out);
}

// round 11
// speedup vs baseline: 1.8755x; 1.8755x over previous
#include <cuda_runtime.h>
#include <math.h>

#define NB 262144
#define NP 8
#define NT 256
#define NBLOCKS (NB / NT)

__device__ double g_part[NBLOCKS];
__device__ unsigned int g_ticket;

__global__ void __launch_bounds__(NT, 3)
ciou_kernel(const float* __restrict__ A, const float* __restrict__ Bm,
            float* __restrict__ out) {
    const int tid = threadIdx.x;
    const int b   = blockIdx.x * NT + tid;

    double val;
    {
        // ---- load both octagons (registers; const indexing everywhere) ----
        float axv[NP], ayv[NP], bxv[NP], byv[NP];
        const float4* pa4 = (const float4*)(A  + (size_t)b * 16);
        const float4* pb4 = (const float4*)(Bm + (size_t)b * 16);
        #pragma unroll
        for (int i = 0; i < 4; i++) {
            float4 fa = pa4[i], fb = pb4[i];
            axv[2*i]   = fa.x; ayv[2*i]   = fa.y;
            axv[2*i+1] = fa.z; ayv[2*i+1] = fa.w;
            bxv[2*i]   = fb.x; byv[2*i]   = fb.y;
            bxv[2*i+1] = fb.z; byv[2*i+1] = fb.w;
        }

        // ---- shoelace areas (vertices CCW by construction) ----
        float area_a = 0.f, area_b = 0.f;
        #pragma unroll
        for (int i = 0; i < NP; i++) {
            int j = (i + 1) & 7;
            area_a += axv[i]*ayv[j] - ayv[i]*axv[j];
            area_b += bxv[i]*byv[j] - byv[i]*bxv[j];
        }
        area_a *= 0.5f; area_b *= 0.5f;

        // ---- intersection area via Green's theorem + Liang-Barsky ----
        // area(A∩B) = 1/2 * sum over boundary sub-segments of cross(P,Q):
        //   * each A edge clipped to the inside of B
        //   * each B edge clipped to the inside of A
        // Order-independent, branch-free, fully register-resident.
        float acc2 = 0.f;

        // A edges clipped against B's half-planes
        #pragma unroll
        for (int i = 0; i < NP; i++) {
            int ik = (i + 1) & 7;
            float px = axv[i],        py = ayv[i];
            float dx = axv[ik] - px,  dy = ayv[ik] - py;
            float t0 = 0.f, t1 = 1.f;
            #pragma unroll
            for (int j = 0; j < NP; j++) {
                int jk = (j + 1) & 7;
                float ex = bxv[jk] - bxv[j], ey = byv[jk] - byv[j];
                float c0 = ex*(py - byv[j]) - ey*(px - bxv[j]); // f(0)
                float cd = ex*dy - ey*dx;                       // df/dt
                float r  = __fdividef(-c0, cd);
                t0 = (cd > 0.f) ? fmaxf(t0, r) : t0;
                t1 = (cd < 0.f) ? fminf(t1, r) : t1;
                if (cd == 0.f && c0 < 0.f) t0 = 1e30f;          // fully outside
            }
            if (t1 > t0) {
                float qx0 = px + t0*dx, qy0 = py + t0*dy;
                float qx1 = px + t1*dx, qy1 = py + t1*dy;
                acc2 += qx0*qy1 - qy0*qx1;
            }
        }
        // B edges clipped against A's half-planes
        #pragma unroll
        for (int i = 0; i < NP; i++) {
            int ik = (i + 1) & 7;
            float px = bxv[i],        py = byv[i];
            float dx = bxv[ik] - px,  dy = byv[ik] - py;
            float t0 = 0.f, t1 = 1.f;
            #pragma unroll
            for (int j = 0; j < NP; j++) {
                int jk = (j + 1) & 7;
                float ex = axv[jk] - axv[j], ey = ayv[jk] - ayv[j];
                float c0 = ex*(py - ayv[j]) - ey*(px - axv[j]);
                float cd = ex*dy - ey*dx;
                float r  = __fdividef(-c0, cd);
                t0 = (cd > 0.f) ? fmaxf(t0, r) : t0;
                t1 = (cd < 0.f) ? fminf(t1, r) : t1;
                if (cd == 0.f && c0 < 0.f) t0 = 1e30f;
            }
            if (t1 > t0) {
                float qx0 = px + t0*dx, qy0 = py + t0*dy;
                float qx1 = px + t1*dx, qy1 = py + t1*dy;
                acc2 += qx0*qy1 - qy0*qx1;
            }
        }
        float inter = fmaxf(0.5f * acc2, 0.f);

        // ---- convex hull of all 16 points (pure-register Jarvis march) ----
        int   si  = 0;
        float spx = axv[0], spy = ayv[0];
        #pragma unroll
        for (int i = 1; i < 16; i++) {
            float pix = (i < 8) ? axv[i] : bxv[i-8];
            float piy = (i < 8) ? ayv[i] : byv[i-8];
            bool better = (piy < spy) || (piy == spy && pix < spx);
            if (better) { si = i; spx = pix; spy = piy; }
        }
        float acc = 0.f, cpx = spx, cpy = spy;
        #pragma unroll 1
        for (int step = 0; step < 16; step++) {
            int   nxt = -1;
            float vnx = 0.f, vny = 0.f, nd2 = 0.f, nxx = 0.f, nxy = 0.f;
            #pragma unroll
            for (int p = 0; p < 16; p++) {
                float pxp = (p < 8) ? axv[p] : bxv[p-8];
                float pyp = (p < 8) ? ayv[p] : byv[p-8];
                float vx = pxp - cpx, vy = pyp - cpy;
                float d2 = vx*vx + vy*vy;
                if (d2 >= 1e-16f) {
                    bool take;
                    if (nxt < 0) take = true;
                    else {
                        float cr = vnx*vy - vny*vx;
                        take = (cr < 0.f) || (cr == 0.f && d2 > nd2);
                    }
                    if (take) { nxt = p; vnx = vx; vny = vy; nd2 = d2;
                                nxx = pxp; nxy = pyp; }
                }
            }
            if (nxt < 0) break;
            acc += cpx*nxy - cpy*nxx;
            if (nxt == si) break;
            cpx = nxx; cpy = nxy;
        }
        float ch = 0.5f * acc;

        // ---- CIoU ----
        float uni = area_a + area_b - inter;
        float iou = inter / uni;
        val = (double)(iou - (ch - uni) / ch);
    }

    // ---- deterministic block reduction (8 warps) ----
    #pragma unroll
    for (int o = 16; o > 0; o >>= 1)
        val += __shfl_down_sync(0xffffffffu, val, o);
    __shared__ double ws[NT / 32];
    __shared__ bool is_last;
    int lane = threadIdx.x & 31;
    int w    = threadIdx.x >> 5;
    if (lane == 0) ws[w] = val;
    __syncthreads();
    if (w == 0) {
        val = (lane < (NT / 32)) ? ws[lane] : 0.0;
        #pragma unroll
        for (int o = 4; o > 0; o >>= 1)
            val += __shfl_down_sync(0xffffffffu, val, o);
        if (lane == 0) g_part[blockIdx.x] = val;
    }

    // ---- last block folds the partials (deterministic fixed-order sum) ----
    __threadfence();
    if (threadIdx.x == 0) {
        unsigned int t = atomicAdd(&g_ticket, 1u);
        is_last = (t == NBLOCKS - 1);
    }
    __syncthreads();
    if (is_last) {
        __threadfence();
        double v = 0.0;
        for (int i = threadIdx.x; i < NBLOCKS; i += NT) v += g_part[i];
        #pragma unroll
        for (int o = 16; o > 0; o >>= 1)
            v += __shfl_down_sync(0xffffffffu, v, o);
        if (lane == 0) ws[w] = v;
        __syncthreads();
        if (w == 0) {
            v = (lane < (NT / 32)) ? ws[lane] : 0.0;
            #pragma unroll
            for (int o = 4; o > 0; o >>= 1)
                v += __shfl_down_sync(0xffffffffu, v, o);
            if (lane == 0) {
                out[0] = (float)(v / (double)NB);
                g_ticket = 0;   // reset for next graph replay
            }
        }
    }
}

extern "C" void kernel_launch(void* const* d_in, const int* in_sizes, int n_in,
                              void* d_out, int out_size) {
    const float* a = (const float*)d_in[0];
    const float* b = (const float*)d_in[1];
    ciou_kernel<<<NBLOCKS, NT>>>(a, b, (float*)d_out);
}

// round 12
// speedup vs baseline: 2.2151x; 1.1810x over previous
#include <cuda_runtime.h>
#include <math.h>

#define NB 262144
#define NP 8
#define NT 256
#define NBLOCKS (NB / NT)

__device__ double g_part[NBLOCKS];
__device__ unsigned int g_ticket;

__global__ void __launch_bounds__(NT, 3)
ciou_kernel(const float* __restrict__ A, const float* __restrict__ Bm,
            float* __restrict__ out) {
    const int tid = threadIdx.x;
    const int b   = blockIdx.x * NT + tid;

    double val;
    {
        // ---- load both octagons (registers; const indexing everywhere) ----
        float axv[NP], ayv[NP], bxv[NP], byv[NP];
        const float4* pa4 = (const float4*)(A  + (size_t)b * 16);
        const float4* pb4 = (const float4*)(Bm + (size_t)b * 16);
        #pragma unroll
        for (int i = 0; i < 4; i++) {
            float4 fa = pa4[i], fb = pb4[i];
            axv[2*i]   = fa.x; ayv[2*i]   = fa.y;
            axv[2*i+1] = fa.z; ayv[2*i+1] = fa.w;
            bxv[2*i]   = fb.x; byv[2*i]   = fb.y;
            bxv[2*i+1] = fb.z; byv[2*i+1] = fb.w;
        }

        // ---- shoelace areas (vertices CCW by construction) ----
        float area_a = 0.f, area_b = 0.f;
        #pragma unroll
        for (int i = 0; i < NP; i++) {
            int j = (i + 1) & 7;
            area_a += axv[i]*ayv[j] - ayv[i]*axv[j];
            area_b += bxv[i]*byv[j] - byv[i]*bxv[j];
        }
        area_a *= 0.5f; area_b *= 0.5f;

        // ---- intersection area via Green's theorem + Liang-Barsky ----
        // area(A∩B) = 1/2 * sum of cross(P,Q) over boundary sub-segments:
        // each A edge clipped to B, each B edge clipped to A. Half-plane j:
        // c(p) = ex*py - ey*px - kc  (>=0 inside), constants hoisted per poly.
        float acc2 = 0.f;

        {   // --- A edges vs B's half-planes ---
            float pex[NP], pey[NP], pkc[NP];
            #pragma unroll
            for (int j = 0; j < NP; j++) {
                int jk = (j + 1) & 7;
                pex[j] = bxv[jk] - bxv[j];
                pey[j] = byv[jk] - byv[j];
                pkc[j] = pex[j]*byv[j] - pey[j]*bxv[j];
            }
            #pragma unroll
            for (int i = 0; i < NP; i++) {
                int ik = (i + 1) & 7;
                float px = axv[i],        py = ayv[i];
                float dx = axv[ik] - px,  dy = ayv[ik] - py;
                float t0 = 0.f, t1 = 1.f;
                #pragma unroll
                for (int j = 0; j < NP; j++) {
                    float c0 = fmaf(pex[j], py, -fmaf(pey[j], px, pkc[j]));
                    float cd = pex[j]*dy - pey[j]*dx;
                    float r  = __fdividef(-c0, cd);
                    t0 = (cd > 0.f) ? fmaxf(t0, r) : t0;
                    t1 = (cd < 0.f) ? fminf(t1, r) : t1;
                    if (cd == 0.f && c0 < 0.f) t0 = 1e30f;   // fully outside
                }
                if (t1 > t0) {
                    float qx0 = px + t0*dx, qy0 = py + t0*dy;
                    float qx1 = px + t1*dx, qy1 = py + t1*dy;
                    acc2 += qx0*qy1 - qy0*qx1;
                }
            }
        }
        {   // --- B edges vs A's half-planes ---
            float pex[NP], pey[NP], pkc[NP];
            #pragma unroll
            for (int j = 0; j < NP; j++) {
                int jk = (j + 1) & 7;
                pex[j] = axv[jk] - axv[j];
                pey[j] = ayv[jk] - ayv[j];
                pkc[j] = pex[j]*ayv[j] - pey[j]*axv[j];
            }
            #pragma unroll
            for (int i = 0; i < NP; i++) {
                int ik = (i + 1) & 7;
                float px = bxv[i],        py = byv[i];
                float dx = bxv[ik] - px,  dy = byv[ik] - py;
                float t0 = 0.f, t1 = 1.f;
                #pragma unroll
                for (int j = 0; j < NP; j++) {
                    float c0 = fmaf(pex[j], py, -fmaf(pey[j], px, pkc[j]));
                    float cd = pex[j]*dy - pey[j]*dx;
                    float r  = __fdividef(-c0, cd);
                    t0 = (cd > 0.f) ? fmaxf(t0, r) : t0;
                    t1 = (cd < 0.f) ? fminf(t1, r) : t1;
                    if (cd == 0.f && c0 < 0.f) t0 = 1e30f;
                }
                if (t1 > t0) {
                    float qx0 = px + t0*dx, qy0 = py + t0*dy;
                    float qx1 = px + t1*dx, qy1 = py + t1*dy;
                    acc2 += qx0*qy1 - qy0*qx1;
                }
            }
        }
        float inter = fmaxf(0.5f * acc2, 0.f);

        // ---- convex hull of all 16 points (pure-register Jarvis march) ----
        // Tie-break on exact collinearity dropped: measure-zero and
        // area-neutral (collinear points add zero-area steps).
        int   si  = 0;
        float spx = axv[0], spy = ayv[0];
        #pragma unroll
        for (int i = 1; i < 16; i++) {
            float pix = (i < 8) ? axv[i] : bxv[i-8];
            float piy = (i < 8) ? ayv[i] : byv[i-8];
            bool better = (piy < spy) || (piy == spy && pix < spx);
            if (better) { si = i; spx = pix; spy = piy; }
        }
        float acc = 0.f, cpx = spx, cpy = spy;
        #pragma unroll 1
        for (int step = 0; step < 16; step++) {
            int   nxt = -1;
            float vnx = 0.f, vny = 0.f, nxx = 0.f, nxy = 0.f;
            #pragma unroll
            for (int p = 0; p < 16; p++) {
                float pxp = (p < 8) ? axv[p] : bxv[p-8];
                float pyp = (p < 8) ? ayv[p] : byv[p-8];
                float vx = pxp - cpx, vy = pyp - cpy;
                float d2 = vx*vx + vy*vy;
                float cr = vnx*vy - vny*vx;
                bool take = (d2 >= 1e-16f) && (nxt < 0 || cr < 0.f);
                if (take) { nxt = p; vnx = vx; vny = vy;
                            nxx = pxp; nxy = pyp; }
            }
            if (nxt < 0) break;
            acc += cpx*nxy - cpy*nxx;
            if (nxt == si) break;
            cpx = nxx; cpy = nxy;
        }
        float ch = 0.5f * acc;

        // ---- CIoU ----
        float uni = area_a + area_b - inter;
        float iou = inter / uni;
        val = (double)(iou - (ch - uni) / ch);
    }

    // ---- deterministic block reduction (8 warps) ----
    #pragma unroll
    for (int o = 16; o > 0; o >>= 1)
        val += __shfl_down_sync(0xffffffffu, val, o);
    __shared__ double ws[NT / 32];
    __shared__ bool is_last;
    int lane = threadIdx.x & 31;
    int w    = threadIdx.x >> 5;
    if (lane == 0) ws[w] = val;
    __syncthreads();
    if (w == 0) {
        val = (lane < (NT / 32)) ? ws[lane] : 0.0;
        #pragma unroll
        for (int o = 4; o > 0; o >>= 1)
            val += __shfl_down_sync(0xffffffffu, val, o);
        if (lane == 0) g_part[blockIdx.x] = val;
    }

    // ---- last block folds the partials (deterministic fixed-order sum) ----
    __threadfence();
    if (threadIdx.x == 0) {
        unsigned int t = atomicAdd(&g_ticket, 1u);
        is_last = (t == NBLOCKS - 1);
    }
    __syncthreads();
    if (is_last) {
        __threadfence();
        double v = 0.0;
        for (int i = threadIdx.x; i < NBLOCKS; i += NT) v += g_part[i];
        #pragma unroll
        for (int o = 16; o > 0; o >>= 1)
            v += __shfl_down_sync(0xffffffffu, v, o);
        if (lane == 0) ws[w] = v;
        __syncthreads();
        if (w == 0) {
            v = (lane < (NT / 32)) ? ws[lane] : 0.0;
            #pragma unroll
            for (int o = 4; o > 0; o >>= 1)
                v += __shfl_down_sync(0xffffffffu, v, o);
            if (lane == 0) {
                out[0] = (float)(v / (double)NB);
                g_ticket = 0;   // reset for next graph replay
            }
        }
    }
}

extern "C" void kernel_launch(void* const* d_in, const int* in_sizes, int n_in,
                              void* d_out, int out_size) {
    const float* a = (const float*)d_in[0];
    const float* b = (const float*)d_in[1];
    ciou_kernel<<<NBLOCKS, NT>>>(a, b, (float*)d_out);
}

// round 13
// speedup vs baseline: 3.0444x; 1.3744x over previous
#include <cuda_runtime.h>
#include <math.h>

#define NB 262144
#define NP 8
#define NT 256
#define NBLOCKS (NB / NT)

__device__ double g_part[NBLOCKS];
__device__ unsigned int g_ticket;

__global__ void __launch_bounds__(NT, 3)
ciou_kernel(const float* __restrict__ A, const float* __restrict__ Bm,
            float* __restrict__ out) {
    const int tid = threadIdx.x;
    const int b   = blockIdx.x * NT + tid;

    double val;
    {
        // ---- load both octagons (registers; const indexing everywhere) ----
        float axv[NP], ayv[NP], bxv[NP], byv[NP];
        const float4* pa4 = (const float4*)(A  + (size_t)b * 16);
        const float4* pb4 = (const float4*)(Bm + (size_t)b * 16);
        #pragma unroll
        for (int i = 0; i < 4; i++) {
            float4 fa = pa4[i], fb = pb4[i];
            axv[2*i]   = fa.x; ayv[2*i]   = fa.y;
            axv[2*i+1] = fa.z; ayv[2*i+1] = fa.w;
            bxv[2*i]   = fb.x; byv[2*i]   = fb.y;
            bxv[2*i+1] = fb.z; byv[2*i+1] = fb.w;
        }

        // ---- shoelace areas (vertices CCW by construction) ----
        float area_a = 0.f, area_b = 0.f;
        #pragma unroll
        for (int i = 0; i < NP; i++) {
            int j = (i + 1) & 7;
            area_a += axv[i]*ayv[j] - ayv[i]*axv[j];
            area_b += bxv[i]*byv[j] - byv[i]*bxv[j];
        }
        area_a *= 0.5f; area_b *= 0.5f;

        // ---- intersection area via Green's theorem + Liang-Barsky ----
        // area(A∩B) = 1/2 * sum of cross(P,Q) over boundary sub-segments:
        // each A edge clipped to B, each B edge clipped to A. Half-plane j:
        // c(p) = ex*py - ey*px - kc (>=0 inside), constants hoisted per poly.
        // Exact-parallel (cd==0.f) infeasibility is measure-zero and ignored;
        // near-parallel flows correctly through the +-huge quotient.
        float acc2 = 0.f;

        {   // --- A edges vs B's half-planes ---
            float pex[NP], pey[NP], pkc[NP];
            #pragma unroll
            for (int j = 0; j < NP; j++) {
                int jk = (j + 1) & 7;
                pex[j] = bxv[jk] - bxv[j];
                pey[j] = byv[jk] - byv[j];
                pkc[j] = pex[j]*byv[j] - pey[j]*bxv[j];
            }
            #pragma unroll
            for (int i = 0; i < NP; i++) {
                int ik = (i + 1) & 7;
                float px = axv[i],        py = ayv[i];
                float dx = axv[ik] - px,  dy = ayv[ik] - py;
                float t0 = 0.f, t1 = 1.f;
                #pragma unroll
                for (int j = 0; j < NP; j++) {
                    float c0 = fmaf(pex[j], py, -fmaf(pey[j], px, pkc[j]));
                    float cd = pex[j]*dy - pey[j]*dx;
                    float r  = __fdividef(-c0, cd);
                    t0 = (cd > 0.f) ? fmaxf(t0, r) : t0;
                    t1 = (cd < 0.f) ? fminf(t1, r) : t1;
                }
                if (t1 > t0) {
                    float qx0 = px + t0*dx, qy0 = py + t0*dy;
                    float qx1 = px + t1*dx, qy1 = py + t1*dy;
                    acc2 += qx0*qy1 - qy0*qx1;
                }
            }
        }
        {   // --- B edges vs A's half-planes ---
            float pex[NP], pey[NP], pkc[NP];
            #pragma unroll
            for (int j = 0; j < NP; j++) {
                int jk = (j + 1) & 7;
                pex[j] = axv[jk] - axv[j];
                pey[j] = ayv[jk] - ayv[j];
                pkc[j] = pex[j]*ayv[j] - pey[j]*axv[j];
            }
            #pragma unroll
            for (int i = 0; i < NP; i++) {
                int ik = (i + 1) & 7;
                float px = bxv[i],        py = byv[i];
                float dx = bxv[ik] - px,  dy = byv[ik] - py;
                float t0 = 0.f, t1 = 1.f;
                #pragma unroll
                for (int j = 0; j < NP; j++) {
                    float c0 = fmaf(pex[j], py, -fmaf(pey[j], px, pkc[j]));
                    float cd = pex[j]*dy - pey[j]*dx;
                    float r  = __fdividef(-c0, cd);
                    t0 = (cd > 0.f) ? fmaxf(t0, r) : t0;
                    t1 = (cd < 0.f) ? fminf(t1, r) : t1;
                }
                if (t1 > t0) {
                    float qx0 = px + t0*dx, qy0 = py + t0*dy;
                    float qx1 = px + t1*dx, qy1 = py + t1*dy;
                    acc2 += qx0*qy1 - qy0*qx1;
                }
            }
        }
        float inter = fmaxf(0.5f * acc2, 0.f);

        // ---- convex hull of all 16 points (lean register Jarvis march) ----
        // Coincident-point guard via integer p!=cur (duplicates measure-zero);
        // candidate seeded from point 0 (or 1 when cur==0); cp advanced by vn.
        int   si  = 0;
        float spx = axv[0], spy = ayv[0];
        #pragma unroll
        for (int i = 1; i < 16; i++) {
            float pix = (i < 8) ? axv[i] : bxv[i-8];
            float piy = (i < 8) ? ayv[i] : byv[i-8];
            bool better = (piy < spy) || (piy == spy && pix < spx);
            if (better) { si = i; spx = pix; spy = piy; }
        }
        int   cur = si;
        float acc = 0.f, cpx = spx, cpy = spy;
        #pragma unroll 1
        for (int step = 0; step < 16; step++) {
            int   nxt = (cur == 0) ? 1 : 0;
            float vnx = ((cur == 0) ? axv[1] : axv[0]) - cpx;
            float vny = ((cur == 0) ? ayv[1] : ayv[0]) - cpy;
            #pragma unroll
            for (int p = 0; p < 16; p++) {
                float pxp = (p < 8) ? axv[p] : bxv[p-8];
                float pyp = (p < 8) ? ayv[p] : byv[p-8];
                float vx = pxp - cpx, vy = pyp - cpy;
                float cr = vnx*vy - vny*vx;
                bool take = (p != cur) && (cr < 0.f);
                if (take) { nxt = p; vnx = vx; vny = vy; }
            }
            acc += cpx*vny - cpy*vnx;    // cross(cp, cp+vn)
            if (nxt == si) break;
            cpx += vnx; cpy += vny;
            cur = nxt;
        }
        float ch = 0.5f * acc;

        // ---- CIoU ----
        float uni = area_a + area_b - inter;
        float iou = inter / uni;
        val = (double)(iou - (ch - uni) / ch);
    }

    // ---- deterministic block reduction (8 warps) ----
    #pragma unroll
    for (int o = 16; o > 0; o >>= 1)
        val += __shfl_down_sync(0xffffffffu, val, o);
    __shared__ double ws[NT / 32];
    __shared__ bool is_last;
    int lane = threadIdx.x & 31;
    int w    = threadIdx.x >> 5;
    if (lane == 0) ws[w] = val;
    __syncthreads();
    if (w == 0) {
        val = (lane < (NT / 32)) ? ws[lane] : 0.0;
        #pragma unroll
        for (int o = 4; o > 0; o >>= 1)
            val += __shfl_down_sync(0xffffffffu, val, o);
        if (lane == 0) g_part[blockIdx.x] = val;
    }

    // ---- last block folds the partials (deterministic fixed-order sum) ----
    __threadfence();
    if (threadIdx.x == 0) {
        unsigned int t = atomicAdd(&g_ticket, 1u);
        is_last = (t == NBLOCKS - 1);
    }
    __syncthreads();
    if (is_last) {
        __threadfence();
        double v = 0.0;
        for (int i = threadIdx.x; i < NBLOCKS; i += NT) v += g_part[i];
        #pragma unroll
        for (int o = 16; o > 0; o >>= 1)
            v += __shfl_down_sync(0xffffffffu, v, o);
        if (lane == 0) ws[w] = v;
        __syncthreads();
        if (w == 0) {
            v = (lane < (NT / 32)) ? ws[lane] : 0.0;
            #pragma unroll
            for (int o = 4; o > 0; o >>= 1)
                v += __shfl_down_sync(0xffffffffu, v, o);
            if (lane == 0) {
                out[0] = (float)(v / (double)NB);
                g_ticket = 0;   // reset for next graph replay
            }
        }
    }
}

extern "C" void kernel_launch(void* const* d_in, const int* in_sizes, int n_in,
                              void* d_out, int out_size) {
    const float* a = (const float*)d_in[0];
    const float* b = (const float*)d_in[1];
    ciou_kernel<<<NBLOCKS, NT>>>(a, b, (float*)d_out);
}

// round 14
// speedup vs baseline: 3.2484x; 1.0670x over previous
#include <cuda_runtime.h>
#include <math.h>

#define NB 262144
#define NP 8
#define NT 256
#define NBLOCKS (NB / NT)

__device__ double g_part[NBLOCKS];
__device__ unsigned int g_ticket;

__global__ void __launch_bounds__(NT, 3)
ciou_kernel(const float* __restrict__ A, const float* __restrict__ Bm,
            float* __restrict__ out) {
    const int tid = threadIdx.x;
    const int b   = blockIdx.x * NT + tid;

    double val;
    {
        // ---- load both octagons (registers; const indexing everywhere) ----
        float axv[NP], ayv[NP], bxv[NP], byv[NP];
        const float4* pa4 = (const float4*)(A  + (size_t)b * 16);
        const float4* pb4 = (const float4*)(Bm + (size_t)b * 16);
        #pragma unroll
        for (int i = 0; i < 4; i++) {
            float4 fa = pa4[i], fb = pb4[i];
            axv[2*i]   = fa.x; ayv[2*i]   = fa.y;
            axv[2*i+1] = fa.z; ayv[2*i+1] = fa.w;
            bxv[2*i]   = fb.x; byv[2*i]   = fb.y;
            bxv[2*i+1] = fb.z; byv[2*i+1] = fb.w;
        }

        // ---- shoelace areas (vertices CCW by construction) ----
        float area_a = 0.f, area_b = 0.f;
        #pragma unroll
        for (int i = 0; i < NP; i++) {
            int j = (i + 1) & 7;
            area_a += axv[i]*ayv[j] - ayv[i]*axv[j];
            area_b += bxv[i]*byv[j] - byv[i]*bxv[j];
        }
        area_a *= 0.5f; area_b *= 0.5f;

        // ---- intersection area via Green's theorem + Liang-Barsky ----
        // Interval update is select-free: g = cd*1e38 carries cd's sign as
        // +-huge/inf, gating r into the max (entering) or min (leaving) bound
        // through pure FMNMX. cd==0.f exactly is measure-zero; near-parallel
        // flows correctly through the +-huge quotient.
        float acc2 = 0.f;

        {   // --- A edges vs B's half-planes ---
            float pex[NP], pey[NP], pkc[NP];
            #pragma unroll
            for (int j = 0; j < NP; j++) {
                int jk = (j + 1) & 7;
                pex[j] = bxv[jk] - bxv[j];
                pey[j] = byv[jk] - byv[j];
                pkc[j] = pex[j]*byv[j] - pey[j]*bxv[j];
            }
            #pragma unroll
            for (int i = 0; i < NP; i++) {
                int ik = (i + 1) & 7;
                float px = axv[i],        py = ayv[i];
                float dx = axv[ik] - px,  dy = ayv[ik] - py;
                float t0 = 0.f, t1 = 1.f;
                #pragma unroll
                for (int j = 0; j < NP; j++) {
                    float c0 = fmaf(pex[j], py, -fmaf(pey[j], px, pkc[j]));
                    float cd = pex[j]*dy - pey[j]*dx;
                    float r  = __fdividef(-c0, cd);
                    float g  = cd * 1e38f;
                    t0 = fmaxf(t0, fminf(r, g));
                    t1 = fminf(t1, fmaxf(r, g));
                }
                if (t1 > t0) {
                    float qx0 = fmaf(t0, dx, px), qy0 = fmaf(t0, dy, py);
                    float qx1 = fmaf(t1, dx, px), qy1 = fmaf(t1, dy, py);
                    acc2 += qx0*qy1 - qy0*qx1;
                }
            }
        }
        {   // --- B edges vs A's half-planes ---
            float pex[NP], pey[NP], pkc[NP];
            #pragma unroll
            for (int j = 0; j < NP; j++) {
                int jk = (j + 1) & 7;
                pex[j] = axv[jk] - axv[j];
                pey[j] = ayv[jk] - ayv[j];
                pkc[j] = pex[j]*ayv[j] - pey[j]*axv[j];
            }
            #pragma unroll
            for (int i = 0; i < NP; i++) {
                int ik = (i + 1) & 7;
                float px = bxv[i],        py = byv[i];
                float dx = bxv[ik] - px,  dy = byv[ik] - py;
                float t0 = 0.f, t1 = 1.f;
                #pragma unroll
                for (int j = 0; j < NP; j++) {
                    float c0 = fmaf(pex[j], py, -fmaf(pey[j], px, pkc[j]));
                    float cd = pex[j]*dy - pey[j]*dx;
                    float r  = __fdividef(-c0, cd);
                    float g  = cd * 1e38f;
                    t0 = fmaxf(t0, fminf(r, g));
                    t1 = fminf(t1, fmaxf(r, g));
                }
                if (t1 > t0) {
                    float qx0 = fmaf(t0, dx, px), qy0 = fmaf(t0, dy, py);
                    float qx1 = fmaf(t1, dx, px), qy1 = fmaf(t1, dy, py);
                    acc2 += qx0*qy1 - qy0*qx1;
                }
            }
        }
        float inter = fmaxf(0.5f * acc2, 0.f);

        // ---- convex hull of all 16 points (lean register Jarvis march) ----
        int   si  = 0;
        float spx = axv[0], spy = ayv[0];
        #pragma unroll
        for (int i = 1; i < 16; i++) {
            float pix = (i < 8) ? axv[i] : bxv[i-8];
            float piy = (i < 8) ? ayv[i] : byv[i-8];
            bool better = (piy < spy) || (piy == spy && pix < spx);
            if (better) { si = i; spx = pix; spy = piy; }
        }
        int   cur = si;
        float acc = 0.f, cpx = spx, cpy = spy;
        #pragma unroll 1
        for (int step = 0; step < 16; step++) {
            int   nxt = (cur == 0) ? 1 : 0;
            float vnx = ((cur == 0) ? axv[1] : axv[0]) - cpx;
            float vny = ((cur == 0) ? ayv[1] : ayv[0]) - cpy;
            #pragma unroll
            for (int p = 0; p < 16; p++) {
                float pxp = (p < 8) ? axv[p] : bxv[p-8];
                float pyp = (p < 8) ? ayv[p] : byv[p-8];
                float vx = pxp - cpx, vy = pyp - cpy;
                float cr = vnx*vy - vny*vx;
                bool take = (p != cur) && (cr < 0.f);
                if (take) { nxt = p; vnx = vx; vny = vy; }
            }
            acc += cpx*vny - cpy*vnx;    // cross(cp, cp+vn)
            if (nxt == si) break;
            cpx += vnx; cpy += vny;
            cur = nxt;
        }
        float ch = 0.5f * acc;

        // ---- CIoU ----
        float uni = area_a + area_b - inter;
        float iou = inter / uni;
        val = (double)(iou - (ch - uni) / ch);
    }

    // ---- deterministic block reduction (8 warps) ----
    #pragma unroll
    for (int o = 16; o > 0; o >>= 1)
        val += __shfl_down_sync(0xffffffffu, val, o);
    __shared__ double ws[NT / 32];
    __shared__ bool is_last;
    int lane = threadIdx.x & 31;
    int w    = threadIdx.x >> 5;
    if (lane == 0) ws[w] = val;
    __syncthreads();
    if (w == 0) {
        val = (lane < (NT / 32)) ? ws[lane] : 0.0;
        #pragma unroll
        for (int o = 4; o > 0; o >>= 1)
            val += __shfl_down_sync(0xffffffffu, val, o);
        if (lane == 0) g_part[blockIdx.x] = val;
    }

    // ---- last block folds the partials (deterministic fixed-order sum) ----
    __threadfence();
    if (threadIdx.x == 0) {
        unsigned int t = atomicAdd(&g_ticket, 1u);
        is_last = (t == NBLOCKS - 1);
    }
    __syncthreads();
    if (is_last) {
        __threadfence();
        double v = 0.0;
        for (int i = threadIdx.x; i < NBLOCKS; i += NT) v += g_part[i];
        #pragma unroll
        for (int o = 16; o > 0; o >>= 1)
            v += __shfl_down_sync(0xffffffffu, v, o);
        if (lane == 0) ws[w] = v;
        __syncthreads();
        if (w == 0) {
            v = (lane < (NT / 32)) ? ws[lane] : 0.0;
            #pragma unroll
            for (int o = 4; o > 0; o >>= 1)
                v += __shfl_down_sync(0xffffffffu, v, o);
            if (lane == 0) {
                out[0] = (float)(v / (double)NB);
                g_ticket = 0;   // reset for next graph replay
            }
        }
    }
}

extern "C" void kernel_launch(void* const* d_in, const int* in_sizes, int n_in,
                              void* d_out, int out_size) {
    const float* a = (const float*)d_in[0];
    const float* b = (const float*)d_in[1];
    ciou_kernel<<<NBLOCKS, NT>>>(a, b, (float*)d_out);
}